// round 5
// baseline (speedup 1.0000x reference)
#include <cuda_runtime.h>

// ---------------------------------------------------------------------------
// B=16, H=W=1024, ROUTE=(512,256) -> ph=2, pw=4, L=8, NPATCH=128
// scale i: W_i=1024>>i, kh=512>>i, kw=256>>i
// out: [0]=loss, [1..16M]=out_img, [16M+1..32M]=lab_img
// ---------------------------------------------------------------------------

#define NPATCH 128
#define IMG0   16777216
#define NSLOTS 5504   // 1024(s1) + 256(s2) + 128(s3) + 4096(s0)
#define PADV   (0.2f / 200.0f)

__device__ double g_pA[NSLOTS];
__device__ double g_pC[NSLOTS];
__device__ double g_pQ[NSLOTS];
__device__ int    g_mask[NPATCH];

// ---------------------------------------------------------------------------
// Fused per-patch reduction. Scales 1-3 FIRST with streaming (.cs) loads;
// scale 0 (128 MB = pre0+gt0, ~= L2 capacity) LAST with caching loads so it
// is L2-resident when k_write gathers it.
//   blocks [0,1024):    scale1, 8/patch, 4 iters
//   blocks [1024,1280): scale2, 2/patch, 4 iters
//   blocks [1280,1408): scale3, 1/patch, 2 iters
//   blocks [1408,5504): scale0, 32/patch, 4 iters
__global__ void __launch_bounds__(256, 4)
k_reduce(const float* __restrict__ p0, const float* __restrict__ p1,
         const float* __restrict__ p2, const float* __restrict__ p3,
         const float* __restrict__ g0, const float* __restrict__ g1,
         const float* __restrict__ g2, const float* __restrict__ g3)
{
    int bid = blockIdx.x;
    int scale, rel;
    if      (bid < 1024) { scale = 1; rel = bid;        }
    else if (bid < 1280) { scale = 2; rel = bid - 1024; }
    else if (bid < 1408) { scale = 3; rel = bid - 1280; }
    else                 { scale = 0; rel = bid - 1408; }

    const int kwS_t[4]  = {8, 7, 6, 5};   // log2 kw
    const int wS_t[4]   = {10, 9, 8, 7};  // log2 W
    const int bppS_t[4] = {5, 3, 1, 0};   // log2 blocks-per-patch

    int kwS  = kwS_t[scale];
    int wS   = wS_t[scale];
    int bppS = bppS_t[scale];

    const float* pre = (scale == 0) ? p0 : (scale == 1) ? p1 : (scale == 2) ? p2 : p3;
    const float* gt  = (scale == 0) ? g0 : (scale == 1) ? g1 : (scale == 2) ? g2 : g3;

    int patch = rel >> bppS;
    int slice = rel & ((1 << bppS) - 1);
    int b  = patch >> 3;
    int pr = (patch >> 2) & 1;
    int pc = patch & 3;

    int qpwS = kwS - 2;                        // log2 quads-per-row
    int row  = threadIdx.x >> qpwS;
    int col4 = (threadIdx.x & ((1 << qpwS) - 1)) << 2;
    int rpi  = 256 >> qpwS;                    // rows per iteration
    int rpb  = rpi << 2;                       // rows per block (4 iters)
    if (scale == 3) rpb = rpi << 1;            // scale3: 2 iters

    int kh  = 512 >> scale;
    int gy  = pr * kh + slice * rpb + row;
    int gx  = (pc << kwS) + col4;
    int idx = (b << (2 * wS)) + (gy << wS) + gx;

    float4 P[4], G[4];
    int nit;
    if (scale == 0) {                          // caching loads: keep in L2
        P[0] = *(const float4*)(pre + idx);
        G[0] = *(const float4*)(gt  + idx);
        P[1] = *(const float4*)(pre + idx + 4096);
        G[1] = *(const float4*)(gt  + idx + 4096);
        P[2] = *(const float4*)(pre + idx + 8192);
        G[2] = *(const float4*)(gt  + idx + 8192);
        P[3] = *(const float4*)(pre + idx + 12288);
        G[3] = *(const float4*)(gt  + idx + 12288);
        nit = 4;
    } else if (scale != 3) {                   // streaming: don't pollute L2
        P[0] = __ldcs((const float4*)(pre + idx));
        G[0] = __ldcs((const float4*)(gt  + idx));
        P[1] = __ldcs((const float4*)(pre + idx + 4096));
        G[1] = __ldcs((const float4*)(gt  + idx + 4096));
        P[2] = __ldcs((const float4*)(pre + idx + 8192));
        G[2] = __ldcs((const float4*)(gt  + idx + 8192));
        P[3] = __ldcs((const float4*)(pre + idx + 12288));
        G[3] = __ldcs((const float4*)(gt  + idx + 12288));
        nit = 4;
    } else {
        P[0] = __ldcs((const float4*)(pre + idx));
        G[0] = __ldcs((const float4*)(gt  + idx));
        P[1] = __ldcs((const float4*)(pre + idx + 4096));
        G[1] = __ldcs((const float4*)(gt  + idx + 4096));
        nit = 2;
    }

    float sg = 0.f, spp = 0.f, cnt = 0.f, ssq = 0.f;

    #define ACC(pp, gg) { float e = fmaf((gg), -200.0f, (pp));       \
                          ssq = fmaf(e, e, ssq); sg += (gg);         \
                          if (e < 0.0f) { cnt += 1.0f; spp += (pp); } }
    #pragma unroll
    for (int it = 0; it < 4; ++it) {
        if (it < nit) {
            ACC(P[it].x, G[it].x) ACC(P[it].y, G[it].y)
            ACC(P[it].z, G[it].z) ACC(P[it].w, G[it].w)
        }
    }
    #undef ACC

    __shared__ float fA[256], fC[256], fQ[256];
    int tid = threadIdx.x;
    fA[tid] = fmaf(sg, 200.0f, -spp);          // sabs = 200*Sum(g) - Sum_pos(p)
    fC[tid] = cnt;
    fQ[tid] = ssq;
    __syncthreads();

    if (tid < 32) {
        double dA = 0.0, dC = 0.0, dQ = 0.0;
        #pragma unroll
        for (int j = 0; j < 8; ++j) {
            int k = tid + (j << 5);
            dA += (double)fA[k];
            dC += (double)fC[k];
            dQ += (double)fQ[k];
        }
        #pragma unroll
        for (int off = 16; off > 0; off >>= 1) {
            dA += __shfl_down_sync(0xffffffffu, dA, off);
            dC += __shfl_down_sync(0xffffffffu, dC, off);
            dQ += __shfl_down_sync(0xffffffffu, dQ, off);
        }
        if (tid == 0) {
            g_pA[bid] = dA;
            g_pC[bid] = dC;
            g_pQ[bid] = dQ;
        }
    }
}

// ---------------------------------------------------------------------------
// Per-patch argmin + weighted loss. 1 block, 128 threads (one per patch).
__global__ void k_select(float* __restrict__ out)
{
    int t = threadIdx.x;
    __shared__ double num[4];
    __shared__ int    cnt[4];
    if (t < 4) { num[t] = 0.0; cnt[t] = 0; }
    __syncthreads();

    const int base4[4] = {1408, 0, 1024, 1280};
    const int cnt4[4]  = {32, 8, 2, 1};

    double best = 1e300;
    int mi = 0;
    double ssqs[4];
    #pragma unroll
    for (int i = 0; i < 4; ++i) {
        double A = 0.0, C = 0.0, Q = 0.0;
        int s0 = base4[i] + t * cnt4[i];
        for (int s = 0; s < cnt4[i]; ++s) {
            A += g_pA[s0 + s];
            C += g_pC[s0 + s];
            Q += g_pQ[s0 + s];
        }
        ssqs[i] = Q;
        double e = A / (C + (double)0.1f);
        if (e < best) { best = e; mi = i; }   // strict < = first-min (argmin)
    }
    g_mask[t] = mi;
    atomicAdd(&num[mi], ssqs[mi]);
    atomicAdd(&cnt[mi], 1);
    __syncthreads();

    if (t == 0) {
        const double w[4]  = {0.5, 0.25, 0.125, 0.0625};
        const double pe[4] = {131072.0, 32768.0, 8192.0, 2048.0};
        double loss = 0.0;
        #pragma unroll
        for (int i = 0; i < 4; ++i)
            loss += w[i] * (num[i] / ((double)cnt[i] * pe[i] + (double)0.01f));
        out[0] = (float)loss;
    }
}

// ---------------------------------------------------------------------------
// Single-pixel compose value (slow path / edges).
__device__ __forceinline__ void pixel_val(
    int P,
    const float* __restrict__ p0, const float* __restrict__ p1,
    const float* __restrict__ p2, const float* __restrict__ p3,
    const float* __restrict__ g0, const float* __restrict__ g1,
    const float* __restrict__ g2, const float* __restrict__ g3,
    float& o, float& l)
{
    int b  = P >> 20;
    int r  = P & 1048575;
    int Y  = r >> 10;
    int X  = r & 1023;
    int pr = Y >> 9;
    int pc = X >> 8;
    int mi = g_mask[(b << 3) | (pr << 2) | pc];
    int kh = 512 >> mi;
    int kw = 256 >> mi;
    int iy = (Y & 511) - ((512 - kh) >> 1);
    int ix = (X & 255) - ((256 - kw) >> 1);
    o = PADV; l = PADV;
    if ((unsigned)iy < (unsigned)kh && (unsigned)ix < (unsigned)kw) {
        int ws  = 10 - mi;
        int idx = (b << (2 * ws)) + ((pr * kh + iy) << ws)
                + (pc << (8 - mi)) + ix;
        const float* pp = (mi == 0) ? p0 : (mi == 1) ? p1 : (mi == 2) ? p2 : p3;
        const float* gg = (mi == 0) ? g0 : (mi == 1) ? g1 : (mi == 2) ? g2 : g3;
        o = pp[idx] / 200.0f;
        l = (gg[idx] * 200.0f) / 200.0f;
    }
}

// ---------------------------------------------------------------------------
// Compose out_img & lab_img. Thread q computes pixels P=4q+3..4q+6 so the
// output quad (out+1+P0) is 16B-aligned -> direct STG.128 from registers.
// No shared memory. Fast path = all 4 pixels in the same row & patch column
// (all quads except X0&255==255, i.e. 63/64); gathers hit L2 (scale0 cached
// by k_reduce ordering). Edge pixels 0,1,2 and 16777215 handled by last thread.
__global__ void __launch_bounds__(256)
k_write(const float* __restrict__ p0, const float* __restrict__ p1,
        const float* __restrict__ p2, const float* __restrict__ p3,
        const float* __restrict__ g0, const float* __restrict__ g1,
        const float* __restrict__ g2, const float* __restrict__ g3,
        float* __restrict__ out)
{
    int q = blockIdx.x * 256 + threadIdx.x;      // 0..4194303
    float* ob = out + 1;
    float* lb = out + 1 + IMG0;

    if (q == 4194303) {                          // edge pixels
        int Ps[4] = {0, 1, 2, 16777215};
        #pragma unroll
        for (int i = 0; i < 4; ++i) {
            float o, l;
            pixel_val(Ps[i], p0, p1, p2, p3, g0, g1, g2, g3, o, l);
            ob[Ps[i]] = o;
            lb[Ps[i]] = l;
        }
        return;
    }

    int P0 = (q << 2) + 3;
    int b  = P0 >> 20;
    int r  = P0 & 1048575;
    int Y  = r >> 10;
    int X0 = r & 1023;

    float4 vo = make_float4(PADV, PADV, PADV, PADV);
    float4 vl = vo;

    if ((X0 & 255) != 255) {
        // same row, same patch for all 4 pixels
        int pr = Y >> 9;
        int pc = X0 >> 8;
        int mi = g_mask[(b << 3) | (pr << 2) | pc];
        int kh = 512 >> mi;
        int kw = 256 >> mi;
        int iy = (Y & 511) - ((512 - kh) >> 1);
        int ix = (X0 & 255) - ((256 - kw) >> 1);
        bool yin = (unsigned)iy < (unsigned)kh;

        if (yin && ix >= 0 && ix + 3 < kw) {
            int ws  = 10 - mi;
            int idx = (b << (2 * ws)) + ((pr * kh + iy) << ws)
                    + (pc << (8 - mi)) + ix;
            const float* pp = (mi == 0) ? p0 : (mi == 1) ? p1 : (mi == 2) ? p2 : p3;
            const float* gg = (mi == 0) ? g0 : (mi == 1) ? g1 : (mi == 2) ? g2 : g3;
            vo = make_float4(pp[idx] / 200.0f, pp[idx + 1] / 200.0f,
                             pp[idx + 2] / 200.0f, pp[idx + 3] / 200.0f);
            vl = make_float4((gg[idx]     * 200.0f) / 200.0f,
                             (gg[idx + 1] * 200.0f) / 200.0f,
                             (gg[idx + 2] * 200.0f) / 200.0f,
                             (gg[idx + 3] * 200.0f) / 200.0f);
        } else if (yin && ix + 3 >= 0 && ix < kw) {
            // x-straddle (ix==-1 or ix==kw-1): per-pixel inside test
            int ws  = 10 - mi;
            const float* pp = (mi == 0) ? p0 : (mi == 1) ? p1 : (mi == 2) ? p2 : p3;
            const float* gg = (mi == 0) ? g0 : (mi == 1) ? g1 : (mi == 2) ? g2 : g3;
            float o[4], l[4];
            #pragma unroll
            for (int j = 0; j < 4; ++j) {
                int ixj = ix + j;
                o[j] = PADV; l[j] = PADV;
                if ((unsigned)ixj < (unsigned)kw) {
                    int idx = (b << (2 * ws)) + ((pr * kh + iy) << ws)
                            + (pc << (8 - mi)) + ixj;
                    o[j] = pp[idx] / 200.0f;
                    l[j] = (gg[idx] * 200.0f) / 200.0f;
                }
            }
            vo = make_float4(o[0], o[1], o[2], o[3]);
            vl = make_float4(l[0], l[1], l[2], l[3]);
        }
        // else: fully outside -> PADV (already set)
    } else {
        // crosses patch column (and possibly row/batch): full per-pixel
        float o[4], l[4];
        #pragma unroll
        for (int j = 0; j < 4; ++j)
            pixel_val(P0 + j, p0, p1, p2, p3, g0, g1, g2, g3, o[j], l[j]);
        vo = make_float4(o[0], o[1], o[2], o[3]);
        vl = make_float4(l[0], l[1], l[2], l[3]);
    }

    __stcs((float4*)(ob + P0), vo);
    __stcs((float4*)(lb + P0), vl);
}

// ---------------------------------------------------------------------------
extern "C" void kernel_launch(void* const* d_in, const int* in_sizes, int n_in,
                              void* d_out, int out_size)
{
    const float *pre[4], *gt[4];
    if (n_in >= 8 && in_sizes[1] == in_sizes[0]) {        // interleaved
        for (int i = 0; i < 4; ++i) {
            pre[i] = (const float*)d_in[2 * i];
            gt [i] = (const float*)d_in[2 * i + 1];
        }
    } else {                                              // grouped
        for (int i = 0; i < 4; ++i) {
            pre[i] = (const float*)d_in[i];
            gt [i] = (const float*)d_in[4 + i];
        }
    }
    float* out = (float*)d_out;

    k_reduce<<<NSLOTS, 256>>>(pre[0], pre[1], pre[2], pre[3],
                              gt[0], gt[1], gt[2], gt[3]);
    k_select<<<1, 128>>>(out);
    k_write<<<16384, 256>>>(pre[0], pre[1], pre[2], pre[3],
                            gt[0], gt[1], gt[2], gt[3], out);
    (void)out_size;
}

// round 6
// speedup vs baseline: 1.0459x; 1.0459x over previous
#include <cuda_runtime.h>

// ---------------------------------------------------------------------------
// B=16, H=W=1024, ROUTE=(512,256) -> ph=2, pw=4, L=8, NPATCH=128
// scale i: W_i=1024>>i, kh=512>>i, kw=256>>i
// out: [0]=loss, [1..16M]=out_img, [16M+1..32M]=lab_img
// ---------------------------------------------------------------------------

#define NPATCH 128
#define IMG0   16777216
#define NSLOTS 5504   // 1024(s1) + 256(s2) + 128(s3) + 4096(s0)
#define PADV   (0.2f / 200.0f)

__device__ double g_pA[NSLOTS];
__device__ double g_pC[NSLOTS];
__device__ double g_pQ[NSLOTS];
__device__ int    g_mask[NPATCH];

// ---------------------------------------------------------------------------
// Fused per-patch reduction. Scales 1-3 first with streaming loads; scale 0
// (128 MB ~= L2) last with caching loads so k_write's gathers can hit L2.
__global__ void __launch_bounds__(256, 4)
k_reduce(const float* __restrict__ p0, const float* __restrict__ p1,
         const float* __restrict__ p2, const float* __restrict__ p3,
         const float* __restrict__ g0, const float* __restrict__ g1,
         const float* __restrict__ g2, const float* __restrict__ g3)
{
    int bid = blockIdx.x;
    int scale, rel;
    if      (bid < 1024) { scale = 1; rel = bid;        }
    else if (bid < 1280) { scale = 2; rel = bid - 1024; }
    else if (bid < 1408) { scale = 3; rel = bid - 1280; }
    else                 { scale = 0; rel = bid - 1408; }

    const int kwS_t[4]  = {8, 7, 6, 5};
    const int wS_t[4]   = {10, 9, 8, 7};
    const int bppS_t[4] = {5, 3, 1, 0};

    int kwS  = kwS_t[scale];
    int wS   = wS_t[scale];
    int bppS = bppS_t[scale];

    const float* pre = (scale == 0) ? p0 : (scale == 1) ? p1 : (scale == 2) ? p2 : p3;
    const float* gt  = (scale == 0) ? g0 : (scale == 1) ? g1 : (scale == 2) ? g2 : g3;

    int patch = rel >> bppS;
    int slice = rel & ((1 << bppS) - 1);
    int b  = patch >> 3;
    int pr = (patch >> 2) & 1;
    int pc = patch & 3;

    int qpwS = kwS - 2;
    int row  = threadIdx.x >> qpwS;
    int col4 = (threadIdx.x & ((1 << qpwS) - 1)) << 2;
    int rpi  = 256 >> qpwS;
    int rpb  = rpi << 2;
    if (scale == 3) rpb = rpi << 1;

    int kh  = 512 >> scale;
    int gy  = pr * kh + slice * rpb + row;
    int gx  = (pc << kwS) + col4;
    int idx = (b << (2 * wS)) + (gy << wS) + gx;

    float4 P[4], G[4];
    int nit;
    if (scale == 0) {
        P[0] = *(const float4*)(pre + idx);
        G[0] = *(const float4*)(gt  + idx);
        P[1] = *(const float4*)(pre + idx + 4096);
        G[1] = *(const float4*)(gt  + idx + 4096);
        P[2] = *(const float4*)(pre + idx + 8192);
        G[2] = *(const float4*)(gt  + idx + 8192);
        P[3] = *(const float4*)(pre + idx + 12288);
        G[3] = *(const float4*)(gt  + idx + 12288);
        nit = 4;
    } else if (scale != 3) {
        P[0] = __ldcs((const float4*)(pre + idx));
        G[0] = __ldcs((const float4*)(gt  + idx));
        P[1] = __ldcs((const float4*)(pre + idx + 4096));
        G[1] = __ldcs((const float4*)(gt  + idx + 4096));
        P[2] = __ldcs((const float4*)(pre + idx + 8192));
        G[2] = __ldcs((const float4*)(gt  + idx + 8192));
        P[3] = __ldcs((const float4*)(pre + idx + 12288));
        G[3] = __ldcs((const float4*)(gt  + idx + 12288));
        nit = 4;
    } else {
        P[0] = __ldcs((const float4*)(pre + idx));
        G[0] = __ldcs((const float4*)(gt  + idx));
        P[1] = __ldcs((const float4*)(pre + idx + 4096));
        G[1] = __ldcs((const float4*)(gt  + idx + 4096));
        nit = 2;
    }

    float sg = 0.f, spp = 0.f, cnt = 0.f, ssq = 0.f;

    #define ACC(pp, gg) { float e = fmaf((gg), -200.0f, (pp));       \
                          ssq = fmaf(e, e, ssq); sg += (gg);         \
                          if (e < 0.0f) { cnt += 1.0f; spp += (pp); } }
    #pragma unroll
    for (int it = 0; it < 4; ++it) {
        if (it < nit) {
            ACC(P[it].x, G[it].x) ACC(P[it].y, G[it].y)
            ACC(P[it].z, G[it].z) ACC(P[it].w, G[it].w)
        }
    }
    #undef ACC

    __shared__ float fA[256], fC[256], fQ[256];
    int tid = threadIdx.x;
    fA[tid] = fmaf(sg, 200.0f, -spp);
    fC[tid] = cnt;
    fQ[tid] = ssq;
    __syncthreads();

    if (tid < 32) {
        double dA = 0.0, dC = 0.0, dQ = 0.0;
        #pragma unroll
        for (int j = 0; j < 8; ++j) {
            int k = tid + (j << 5);
            dA += (double)fA[k];
            dC += (double)fC[k];
            dQ += (double)fQ[k];
        }
        #pragma unroll
        for (int off = 16; off > 0; off >>= 1) {
            dA += __shfl_down_sync(0xffffffffu, dA, off);
            dC += __shfl_down_sync(0xffffffffu, dC, off);
            dQ += __shfl_down_sync(0xffffffffu, dQ, off);
        }
        if (tid == 0) {
            g_pA[bid] = dA;
            g_pC[bid] = dC;
            g_pQ[bid] = dQ;
        }
    }
}

// ---------------------------------------------------------------------------
__global__ void k_select(float* __restrict__ out)
{
    int t = threadIdx.x;
    __shared__ double num[4];
    __shared__ int    cnt[4];
    if (t < 4) { num[t] = 0.0; cnt[t] = 0; }
    __syncthreads();

    const int base4[4] = {1408, 0, 1024, 1280};
    const int cnt4[4]  = {32, 8, 2, 1};

    double best = 1e300;
    int mi = 0;
    double ssqs[4];
    #pragma unroll
    for (int i = 0; i < 4; ++i) {
        double A = 0.0, C = 0.0, Q = 0.0;
        int s0 = base4[i] + t * cnt4[i];
        for (int s = 0; s < cnt4[i]; ++s) {
            A += g_pA[s0 + s];
            C += g_pC[s0 + s];
            Q += g_pQ[s0 + s];
        }
        ssqs[i] = Q;
        double e = A / (C + (double)0.1f);
        if (e < best) { best = e; mi = i; }
    }
    g_mask[t] = mi;
    atomicAdd(&num[mi], ssqs[mi]);
    atomicAdd(&cnt[mi], 1);
    __syncthreads();

    if (t == 0) {
        const double w[4]  = {0.5, 0.25, 0.125, 0.0625};
        const double pe[4] = {131072.0, 32768.0, 8192.0, 2048.0};
        double loss = 0.0;
        #pragma unroll
        for (int i = 0; i < 4; ++i)
            loss += w[i] * (num[i] / ((double)cnt[i] * pe[i] + (double)0.01f));
        out[0] = (float)loss;
    }
}

// ---------------------------------------------------------------------------
// Single-pixel compose value (edges / block-boundary recompute).
__device__ __forceinline__ void pixel_val(
    int P,
    const float* __restrict__ p0, const float* __restrict__ p1,
    const float* __restrict__ p2, const float* __restrict__ p3,
    const float* __restrict__ g0, const float* __restrict__ g1,
    const float* __restrict__ g2, const float* __restrict__ g3,
    float& o, float& l)
{
    int b  = P >> 20;
    int r  = P & 1048575;
    int Y  = r >> 10;
    int X  = r & 1023;
    int pr = Y >> 9;
    int pc = X >> 8;
    int mi = g_mask[(b << 3) | (pr << 2) | pc];
    int kh = 512 >> mi;
    int kw = 256 >> mi;
    int iy = (Y & 511) - ((512 - kh) >> 1);
    int ix = (X & 255) - ((256 - kw) >> 1);
    o = PADV; l = PADV;
    if ((unsigned)iy < (unsigned)kh && (unsigned)ix < (unsigned)kw) {
        int ws  = 10 - mi;
        int idx = (b << (2 * ws)) + ((pr * kh + iy) << ws)
                + (pc << (8 - mi)) + ix;
        const float* pp = (mi == 0) ? p0 : (mi == 1) ? p1 : (mi == 2) ? p2 : p3;
        const float* gg = (mi == 0) ? g0 : (mi == 1) ? g1 : (mi == 2) ? g2 : g3;
        o = pp[idx] / 200.0f;
        l = (gg[idx] * 200.0f) / 200.0f;
    }
}

// ---------------------------------------------------------------------------
// Compose. Thread g computes the ALIGNED pixel quad [4g,4g+4) with one
// LDG.128 per source (padded widths are ==0 mod 4 so an aligned quad is
// never partially inside a patch). The +1 output shift is realigned by
// warp shuffle: out quad = (my.w, next.xyz), stored as aligned STG.128.
// Lane 31 gets "next" from a per-warp smem publish; the last thread of
// each block recomputes the next block's 3 leading pixels scalar.
__global__ void __launch_bounds__(256)
k_write(const float* __restrict__ p0, const float* __restrict__ p1,
        const float* __restrict__ p2, const float* __restrict__ p3,
        const float* __restrict__ g0, const float* __restrict__ g1,
        const float* __restrict__ g2, const float* __restrict__ g3,
        float* __restrict__ out)
{
    __shared__ float s_pub[8][6];                 // lane-0 xyz of vo and vl

    int tid = threadIdx.x;
    int g   = blockIdx.x * 256 + tid;             // quad id, 0..4194303
    int lane = tid & 31;
    int wrp  = tid >> 5;

    int P0 = g << 2;                              // aligned pixel base
    int b  = P0 >> 20;
    int r  = P0 & 1048575;
    int Y  = r >> 10;
    int X  = r & 1023;
    int pr = Y >> 9;
    int pc = X >> 8;
    int mi = g_mask[(b << 3) | (pr << 2) | pc];

    int kh = 512 >> mi;
    int kw = 256 >> mi;
    int iy = (Y & 511) - ((512 - kh) >> 1);
    int ix = (X & 255) - ((256 - kw) >> 1);       // multiple of 4

    float4 vo = make_float4(PADV, PADV, PADV, PADV);
    float4 vl = vo;

    if ((unsigned)iy < (unsigned)kh && (unsigned)ix < (unsigned)kw) {
        int ws  = 10 - mi;
        int idx = (b << (2 * ws)) + ((pr * kh + iy) << ws)
                + (pc << (8 - mi)) + ix;          // 16B aligned
        const float* pp = (mi == 0) ? p0 : (mi == 1) ? p1 : (mi == 2) ? p2 : p3;
        const float* gg = (mi == 0) ? g0 : (mi == 1) ? g1 : (mi == 2) ? g2 : g3;
        float4 p = *(const float4*)(pp + idx);
        float4 q = *(const float4*)(gg + idx);
        vo = make_float4(p.x / 200.0f, p.y / 200.0f, p.z / 200.0f, p.w / 200.0f);
        vl = make_float4((q.x * 200.0f) / 200.0f, (q.y * 200.0f) / 200.0f,
                         (q.z * 200.0f) / 200.0f, (q.w * 200.0f) / 200.0f);
    }

    if (lane == 0) {
        s_pub[wrp][0] = vo.x; s_pub[wrp][1] = vo.y; s_pub[wrp][2] = vo.z;
        s_pub[wrp][3] = vl.x; s_pub[wrp][4] = vl.y; s_pub[wrp][5] = vl.z;
    }
    __syncthreads();

    // neighbor xyz via shuffle (all lanes participate)
    float nox = __shfl_down_sync(0xffffffffu, vo.x, 1);
    float noy = __shfl_down_sync(0xffffffffu, vo.y, 1);
    float noz = __shfl_down_sync(0xffffffffu, vo.z, 1);
    float nlx = __shfl_down_sync(0xffffffffu, vl.x, 1);
    float nly = __shfl_down_sync(0xffffffffu, vl.y, 1);
    float nlz = __shfl_down_sync(0xffffffffu, vl.z, 1);

    float* ob = out + 1;
    float* lb = out + 1 + IMG0;

    bool lastThread = (tid == 255);
    bool lastGlobal = (g == 4194303);

    if (lane == 31) {
        if (!lastThread) {
            nox = s_pub[wrp + 1][0]; noy = s_pub[wrp + 1][1]; noz = s_pub[wrp + 1][2];
            nlx = s_pub[wrp + 1][3]; nly = s_pub[wrp + 1][4]; nlz = s_pub[wrp + 1][5];
        } else if (!lastGlobal) {
            int Pn = (g + 1) << 2;                // next block's first 3 pixels
            pixel_val(Pn,     p0, p1, p2, p3, g0, g1, g2, g3, nox, nlx);
            pixel_val(Pn + 1, p0, p1, p2, p3, g0, g1, g2, g3, noy, nly);
            pixel_val(Pn + 2, p0, p1, p2, p3, g0, g1, g2, g3, noz, nlz);
        }
    }

    if (!lastGlobal) {
        int k = P0 + 3;                           // ob+k globally 16B aligned
        __stcs((float4*)(ob + k), make_float4(vo.w, nox, noy, noz));
        __stcs((float4*)(lb + k), make_float4(vl.w, nlx, nly, nlz));
    } else {
        ob[16777215] = vo.w;
        lb[16777215] = vl.w;
    }

    if (g == 0) {                                 // leading 3 out pixels
        ob[0] = vo.x; ob[1] = vo.y; ob[2] = vo.z;
        lb[0] = vl.x; lb[1] = vl.y; lb[2] = vl.z;
    }
}

// ---------------------------------------------------------------------------
extern "C" void kernel_launch(void* const* d_in, const int* in_sizes, int n_in,
                              void* d_out, int out_size)
{
    const float *pre[4], *gt[4];
    if (n_in >= 8 && in_sizes[1] == in_sizes[0]) {        // interleaved
        for (int i = 0; i < 4; ++i) {
            pre[i] = (const float*)d_in[2 * i];
            gt [i] = (const float*)d_in[2 * i + 1];
        }
    } else {                                              // grouped
        for (int i = 0; i < 4; ++i) {
            pre[i] = (const float*)d_in[i];
            gt [i] = (const float*)d_in[4 + i];
        }
    }
    float* out = (float*)d_out;

    k_reduce<<<NSLOTS, 256>>>(pre[0], pre[1], pre[2], pre[3],
                              gt[0], gt[1], gt[2], gt[3]);
    k_select<<<1, 128>>>(out);
    k_write<<<16384, 256>>>(pre[0], pre[1], pre[2], pre[3],
                            gt[0], gt[1], gt[2], gt[3], out);
    (void)out_size;
}